// round 6
// baseline (speedup 1.0000x reference)
#include <cuda_runtime.h>
#include <cstdint>

// Problem constants (shapes fixed by the dataset)
#define NNODES 100000
#define NEDGES 1600000
#define NGRAPH 128
#define HDIM   128
#define FDIM   64
#define LN_EPS 1e-5f

#define SCANW   1024
#define NSCANBLK ((NNODES + SCANW) / SCANW + 1)
#define NPARTIAL (NSCANBLK * SCANW)

// packed fp32x2 FMA (Blackwell sm_100): d = a*b + d elementwise on 2xf32
#define FMA2(d, a, b) asm("fma.rn.f32x2 %0, %1, %2, %0;" : "+l"(d) : "l"(a), "l"(b))
#define SPLAT2(o, f)  asm("mov.b64 %0, {%1, %1};" : "=l"(o) : "f"(f))
#define UNPK2(lo, hi, v) asm("mov.b64 {%0, %1}, %2;" : "=f"(lo), "=f"(hi) : "l"(v))

// ---------------- scratch (device globals; no allocations allowed) ----------
__device__ int   g_ibuf[NPARTIAL + NNODES];         // deg + fill cursors (one memset)
__device__ int   g_partial[NPARTIAL];               // per-block exclusive scan
__device__ int   g_blocksum[256];
__device__ int2  g_csr[NEDGES];                     // (src, bits(dinv[src]))
__device__ float g_bufa[(size_t)NNODES * HDIM];
__device__ float g_bufb[(size_t)NNODES * HDIM];
__device__ float g_pool[NGRAPH * HDIM + NGRAPH];    // gsum + gcnt (one memset)

// ---------------- degree count ----------------
__global__ void k_count_deg(const int* __restrict__ dst, int* __restrict__ deg, int e) {
    int i = blockIdx.x * blockDim.x + threadIdx.x;
    if (i < e) atomicAdd(&deg[dst[i]], 1);
}

// ---------------- per-block exclusive scan (level 1) ----------------
__global__ void k_scan_block(const int* __restrict__ deg, int* __restrict__ partial,
                             int* __restrict__ blocksum, int n) {
    __shared__ int sm[2][SCANW];
    int t = threadIdx.x;
    int g = blockIdx.x * SCANW + t;
    int v = (g < n) ? deg[g] : 0;
    sm[0][t] = v;
    __syncthreads();
    int cur = 0;
#pragma unroll
    for (int off = 1; off < SCANW; off <<= 1) {
        int x = sm[cur][t];
        if (t >= off) x += sm[cur][t - off];
        sm[cur ^ 1][t] = x;
        __syncthreads();
        cur ^= 1;
    }
    int inc = sm[cur][t];
    partial[g] = inc - v;
    if (t == SCANW - 1) blocksum[blockIdx.x] = inc;
}

// Level-2 prefix computed IN-BLOCK by every consumer (<=128 scan blocks).
// Must be called by all threads of a 256-thread block before any early return.
__device__ __forceinline__ void block_prefix(const int* __restrict__ bsum, int B,
                                             int* __restrict__ sbp) {
    __shared__ int tmp[128];
    int t = threadIdx.x;
    int v = 0;
    if (t < 128) { v = (t < B) ? bsum[t] : 0; tmp[t] = v; }
    __syncthreads();
#pragma unroll
    for (int off = 1; off < 128; off <<= 1) {
        int x = 0;
        if (t < 128) { x = tmp[t]; if (t >= off) x += tmp[t - off]; }
        __syncthreads();
        if (t < 128) tmp[t] = x;
        __syncthreads();
    }
    if (t < 128) sbp[t] = tmp[t] - v;   // exclusive
    __syncthreads();
}

// ---------------- CSR fill: csr[pos] = (src, dinv[src]) ordered by dst ------
__global__ void __launch_bounds__(256)
k_fill(const int* __restrict__ src, const int* __restrict__ dst,
       const int* __restrict__ deg, const int* __restrict__ partial,
       const int* __restrict__ bsum, int B,
       int* __restrict__ cnt2, int2* __restrict__ csr, int e) {
    __shared__ int sbp[128];
    block_prefix(bsum, B, sbp);
    int i = blockIdx.x * blockDim.x + threadIdx.x;
    if (i >= e) return;
    int s = src[i];
    int d = dst[i];
    float dvs = rsqrtf((float)(deg[s] + 1));
    int pos = partial[d] + sbp[d >> 10] + atomicAdd(&cnt2[d], 1);
    csr[pos] = make_int2(s, __float_as_int(dvs));
}

// ---------------- gather aggregation: warp per dst node ---------------------
// out[v] = dinv[v] * ( sum_{s in N(v)} dinv[s]*feat[s] + dinv[v]*feat[v] )
__global__ void __launch_bounds__(256)
k_agg64(const float* __restrict__ feat, const int* __restrict__ deg,
        const int2* __restrict__ csr, const int* __restrict__ partial,
        const int* __restrict__ bsum, int B, float* __restrict__ out, int n) {
    __shared__ int sbp[128];
    block_prefix(bsum, B, sbp);
    int w = (blockIdx.x * blockDim.x + threadIdx.x) >> 5;
    if (w >= n) return;
    int lane = threadIdx.x & 31;
    int r0 = partial[w] + sbp[w >> 10];
    int r1 = partial[w + 1] + sbp[(w + 1) >> 10];
    float dv = rsqrtf((float)(deg[w] + 1));

    float2 acc = reinterpret_cast<const float2*>(feat)[(size_t)w * 32 + lane];
    acc.x *= dv; acc.y *= dv;

    int r = r0;
    for (; r + 4 <= r1; r += 4) {
        int2 e0 = csr[r], e1 = csr[r + 1], e2 = csr[r + 2], e3 = csr[r + 3];
        float2 v0 = reinterpret_cast<const float2*>(feat)[(size_t)e0.x * 32 + lane];
        float2 v1 = reinterpret_cast<const float2*>(feat)[(size_t)e1.x * 32 + lane];
        float2 v2 = reinterpret_cast<const float2*>(feat)[(size_t)e2.x * 32 + lane];
        float2 v3 = reinterpret_cast<const float2*>(feat)[(size_t)e3.x * 32 + lane];
        float w0 = __int_as_float(e0.y), w1 = __int_as_float(e1.y);
        float w2 = __int_as_float(e2.y), w3 = __int_as_float(e3.y);
        acc.x = fmaf(w0, v0.x, acc.x); acc.y = fmaf(w0, v0.y, acc.y);
        acc.x = fmaf(w1, v1.x, acc.x); acc.y = fmaf(w1, v1.y, acc.y);
        acc.x = fmaf(w2, v2.x, acc.x); acc.y = fmaf(w2, v2.y, acc.y);
        acc.x = fmaf(w3, v3.x, acc.x); acc.y = fmaf(w3, v3.y, acc.y);
    }
    for (; r < r1; r++) {
        int2 e0 = csr[r];
        float2 v0 = reinterpret_cast<const float2*>(feat)[(size_t)e0.x * 32 + lane];
        float w0 = __int_as_float(e0.y);
        acc.x = fmaf(w0, v0.x, acc.x); acc.y = fmaf(w0, v0.y, acc.y);
    }
    acc.x *= dv; acc.y *= dv;
    reinterpret_cast<float2*>(out)[(size_t)w * 32 + lane] = acc;
}

__global__ void __launch_bounds__(256)
k_agg128(const float* __restrict__ feat, const int* __restrict__ deg,
         const int2* __restrict__ csr, const int* __restrict__ partial,
         const int* __restrict__ bsum, int B, float* __restrict__ out, int n) {
    __shared__ int sbp[128];
    block_prefix(bsum, B, sbp);
    int w = (blockIdx.x * blockDim.x + threadIdx.x) >> 5;
    if (w >= n) return;
    int lane = threadIdx.x & 31;
    int r0 = partial[w] + sbp[w >> 10];
    int r1 = partial[w + 1] + sbp[(w + 1) >> 10];
    float dv = rsqrtf((float)(deg[w] + 1));

    float4 acc = reinterpret_cast<const float4*>(feat)[(size_t)w * 32 + lane];
    acc.x *= dv; acc.y *= dv; acc.z *= dv; acc.w *= dv;

    int r = r0;
    for (; r + 4 <= r1; r += 4) {
        int2 e0 = csr[r], e1 = csr[r + 1], e2 = csr[r + 2], e3 = csr[r + 3];
        float4 v0 = reinterpret_cast<const float4*>(feat)[(size_t)e0.x * 32 + lane];
        float4 v1 = reinterpret_cast<const float4*>(feat)[(size_t)e1.x * 32 + lane];
        float4 v2 = reinterpret_cast<const float4*>(feat)[(size_t)e2.x * 32 + lane];
        float4 v3 = reinterpret_cast<const float4*>(feat)[(size_t)e3.x * 32 + lane];
        float w0 = __int_as_float(e0.y), w1 = __int_as_float(e1.y);
        float w2 = __int_as_float(e2.y), w3 = __int_as_float(e3.y);
        acc.x = fmaf(w0, v0.x, acc.x); acc.y = fmaf(w0, v0.y, acc.y);
        acc.z = fmaf(w0, v0.z, acc.z); acc.w = fmaf(w0, v0.w, acc.w);
        acc.x = fmaf(w1, v1.x, acc.x); acc.y = fmaf(w1, v1.y, acc.y);
        acc.z = fmaf(w1, v1.z, acc.z); acc.w = fmaf(w1, v1.w, acc.w);
        acc.x = fmaf(w2, v2.x, acc.x); acc.y = fmaf(w2, v2.y, acc.y);
        acc.z = fmaf(w2, v2.z, acc.z); acc.w = fmaf(w2, v2.w, acc.w);
        acc.x = fmaf(w3, v3.x, acc.x); acc.y = fmaf(w3, v3.y, acc.y);
        acc.z = fmaf(w3, v3.z, acc.z); acc.w = fmaf(w3, v3.w, acc.w);
    }
    for (; r < r1; r++) {
        int2 e0 = csr[r];
        float4 v0 = reinterpret_cast<const float4*>(feat)[(size_t)e0.x * 32 + lane];
        float w0 = __int_as_float(e0.y);
        acc.x = fmaf(w0, v0.x, acc.x); acc.y = fmaf(w0, v0.y, acc.y);
        acc.z = fmaf(w0, v0.z, acc.z); acc.w = fmaf(w0, v0.w, acc.w);
    }
    acc.x *= dv; acc.y *= dv; acc.z *= dv; acc.w *= dv;
    reinterpret_cast<float4*>(out)[(size_t)w * 32 + lane] = acc;
}

// ---------------- fused GEMM + bias + LayerNorm (+ReLU), fp32x2 packed ------
// Accumulators pack ROW pairs: acc2[rp][c] = (acc[2rp][c], acc[2rp+1][c]).
// x pair comes free from a 64-bit LDS of the transposed X tile.
template <int K, bool RELU>
__global__ void __launch_bounds__(256)
k_gemm_ln(const float* __restrict__ in, const float* __restrict__ W,
          const float* __restrict__ bias, const float* __restrict__ gamma,
          const float* __restrict__ beta, float* __restrict__ out, int nrows) {
    __shared__ __align__(16) float sW[32][128];
    __shared__ __align__(16) float sXT[32][36];   // [k][row], 144B rows (16B-mult)

    const int tid  = threadIdx.x;
    const int warp = tid >> 5;
    const int lane = tid & 31;
    const int row0 = blockIdx.x * 32;
    if (row0 >= nrows) return;

    uint64_t acc2[2][4];
#pragma unroll
    for (int rp = 0; rp < 2; rp++)
#pragma unroll
        for (int c = 0; c < 4; c++) acc2[rp][c] = 0ull;   // two packed 0.0f

#pragma unroll
    for (int kt = 0; kt < K; kt += 32) {
        // W tile: 32x128 floats = 1024 float4, 256 threads -> 4 each
#pragma unroll
        for (int i = tid; i < 1024; i += 256) {
            int kk = i >> 5;
            int c4 = i & 31;
            reinterpret_cast<float4*>(sW[kk])[c4] =
                reinterpret_cast<const float4*>(W + (size_t)(kt + kk) * 128)[c4];
        }
        // X tile transposed
        {
            int r  = tid >> 3;
            int k4 = tid & 7;
            float4 v = reinterpret_cast<const float4*>(in + (size_t)(row0 + r) * K + kt)[k4];
            sXT[k4 * 4 + 0][r] = v.x;
            sXT[k4 * 4 + 1][r] = v.y;
            sXT[k4 * 4 + 2][r] = v.z;
            sXT[k4 * 4 + 3][r] = v.w;
        }
        __syncthreads();

#pragma unroll
        for (int kk = 0; kk < 32; kk++) {
            float4 wv = reinterpret_cast<float4*>(sW[kk])[lane];
            ulonglong2 xp = *reinterpret_cast<const ulonglong2*>(&sXT[kk][warp * 4]);
            uint64_t ws0, ws1, ws2, ws3;
            SPLAT2(ws0, wv.x);
            SPLAT2(ws1, wv.y);
            SPLAT2(ws2, wv.z);
            SPLAT2(ws3, wv.w);
            FMA2(acc2[0][0], xp.x, ws0); FMA2(acc2[1][0], xp.y, ws0);
            FMA2(acc2[0][1], xp.x, ws1); FMA2(acc2[1][1], xp.y, ws1);
            FMA2(acc2[0][2], xp.x, ws2); FMA2(acc2[1][2], xp.y, ws2);
            FMA2(acc2[0][3], xp.x, ws3); FMA2(acc2[1][3], xp.y, ws3);
        }
        __syncthreads();
    }

    // unpack to per-row accumulators
    float acc[4][4];
#pragma unroll
    for (int rp = 0; rp < 2; rp++)
#pragma unroll
        for (int c = 0; c < 4; c++) {
            float lo, hi;
            UNPK2(lo, hi, acc2[rp][c]);
            acc[rp * 2 + 0][c] = lo;
            acc[rp * 2 + 1][c] = hi;
        }

    const float4 bv = reinterpret_cast<const float4*>(bias)[lane];
    const float4 gv = reinterpret_cast<const float4*>(gamma)[lane];
    const float4 be = reinterpret_cast<const float4*>(beta)[lane];

#pragma unroll
    for (int r = 0; r < 4; r++) {
        float hx = acc[r][0] + bv.x;
        float hy = acc[r][1] + bv.y;
        float hz = acc[r][2] + bv.z;
        float hw = acc[r][3] + bv.w;
        float s = hx + hy + hz + hw;
#pragma unroll
        for (int o = 16; o > 0; o >>= 1) s += __shfl_xor_sync(0xffffffffu, s, o);
        float mu = s * (1.0f / 128.0f);
        float dx = hx - mu, dy = hy - mu, dz = hz - mu, dw = hw - mu;
        float q = dx * dx + dy * dy + dz * dz + dw * dw;
#pragma unroll
        for (int o = 16; o > 0; o >>= 1) q += __shfl_xor_sync(0xffffffffu, q, o);
        float rstd = rsqrtf(q * (1.0f / 128.0f) + LN_EPS);

        float4 o4;
        o4.x = dx * rstd * gv.x + be.x;
        o4.y = dy * rstd * gv.y + be.y;
        o4.z = dz * rstd * gv.z + be.z;
        o4.w = dw * rstd * gv.w + be.w;
        if (RELU) {
            o4.x = fmaxf(o4.x, 0.0f);
            o4.y = fmaxf(o4.y, 0.0f);
            o4.z = fmaxf(o4.z, 0.0f);
            o4.w = fmaxf(o4.w, 0.0f);
        }
        int row = row0 + warp * 4 + r;
        reinterpret_cast<float4*>(out + (size_t)row * 128)[lane] = o4;
    }
}

// ---------------- pooling (batch is sorted; count fused) ----------------
__global__ void k_pool_sum(const float* __restrict__ h, const int* __restrict__ batch,
                           float* __restrict__ gsum, int* __restrict__ gcnt, int n, int rpb) {
    int c  = threadIdx.x;
    int r0 = blockIdx.x * rpb;
    int r1 = min(r0 + rpb, n);
    if (r0 >= r1) return;
    float acc = 0.0f;
    int cnt = 0;
    int cur = batch[r0];
    for (int r = r0; r < r1; r++) {
        int g = batch[r];
        if (g != cur) {
            atomicAdd(&gsum[cur * HDIM + c], acc);
            if (c == 0) atomicAdd(&gcnt[cur], cnt);
            acc = 0.0f; cnt = 0; cur = g;
        }
        acc += h[(size_t)r * HDIM + c];
        cnt++;
    }
    atomicAdd(&gsum[cur * HDIM + c], acc);
    if (c == 0) atomicAdd(&gcnt[cur], cnt);
}

__global__ void k_finalize(const float* __restrict__ gsum, const int* __restrict__ gcnt,
                           float* __restrict__ out) {
    int i = blockIdx.x * blockDim.x + threadIdx.x;
    if (i >= NGRAPH * HDIM) return;
    float cnt = fmaxf((float)gcnt[i >> 7], 1.0f);
    out[i] = gsum[i] / cnt;
}

// ---------------- launch ----------------
extern "C" void kernel_launch(void* const* d_in, const int* in_sizes, int n_in,
                              void* d_out, int out_size) {
    const float* x     = (const float*)d_in[0];
    const int*   eidx  = (const int*)d_in[1];
    const int*   batch = (const int*)d_in[2];
    const float* W1 = (const float*)d_in[3];
    const float* b1 = (const float*)d_in[4];
    const float* g1 = (const float*)d_in[5];
    const float* be1 = (const float*)d_in[6];
    const float* W2 = (const float*)d_in[7];
    const float* b2 = (const float*)d_in[8];
    const float* g2 = (const float*)d_in[9];
    const float* be2 = (const float*)d_in[10];

    const int n = in_sizes[0] / FDIM;   // 100000
    const int e = in_sizes[1] / 2;      // 1600000
    const int* src = eidx;
    const int* dst = eidx + e;

    int*   ibuf;  cudaGetSymbolAddress((void**)&ibuf,  g_ibuf);
    int*   part;  cudaGetSymbolAddress((void**)&part,  g_partial);
    int*   bsum;  cudaGetSymbolAddress((void**)&bsum,  g_blocksum);
    int2*  csr;   cudaGetSymbolAddress((void**)&csr,   g_csr);
    float* bufa;  cudaGetSymbolAddress((void**)&bufa,  g_bufa);
    float* bufb;  cudaGetSymbolAddress((void**)&bufb,  g_bufb);
    float* pool;  cudaGetSymbolAddress((void**)&pool,  g_pool);

    int* deg  = ibuf;
    int* cnt2 = ibuf + NPARTIAL;
    float* gsum = pool;
    int*   gcnt = (int*)(pool + NGRAPH * HDIM);

    const int T = 256;
    auto cdiv = [](int a, int b) { return (a + b - 1) / b; };
    const int B = cdiv(n + 1, SCANW);   // scan blocks (covers index n)

    cudaMemsetAsync(ibuf, 0, sizeof(int) * (NPARTIAL + NNODES));
    cudaMemsetAsync(pool, 0, sizeof(float) * (NGRAPH * HDIM) + sizeof(int) * NGRAPH);

    // CSR build (level-2 prefix folded into consumers)
    k_count_deg<<<cdiv(e, T), T>>>(dst, deg, e);                              // 1
    k_scan_block<<<B, SCANW>>>(deg, part, bsum, n);                           // 2
    k_fill<<<cdiv(e, T), T>>>(src, dst, deg, part, bsum, B, cnt2, csr, e);    // 3

    // conv1: gather-aggregate x (64-wide) then GEMM (Agg(xW) == Agg(x)W)
    k_agg64<<<cdiv(n * 32, T), T>>>(x, deg, csr, part, bsum, B, bufa, n);     // 4 <- profiled
    k_gemm_ln<FDIM, true><<<n / 32, T>>>(bufa, W1, b1, g1, be1, bufb, n);     // 5

    // conv2: gather-aggregate h1 (128-wide) then GEMM+LN
    k_agg128<<<cdiv(n * 32, T), T>>>(bufb, deg, csr, part, bsum, B, bufa, n); // 6
    k_gemm_ln<HDIM, false><<<n / 32, T>>>(bufa, W2, b2, g2, be2, bufb, n);    // 7

    // mean pool per graph (batch is sorted)
    const int rpb = 128;
    k_pool_sum<<<cdiv(n, rpb), HDIM>>>(bufb, batch, gsum, gcnt, n, rpb);      // 8
    k_finalize<<<cdiv(NGRAPH * HDIM, HDIM), HDIM>>>(gsum, gcnt, (float*)d_out); // 9
}

// round 7
// speedup vs baseline: 1.0923x; 1.0923x over previous
#include <cuda_runtime.h>
#include <cstdint>

// Problem constants (shapes fixed by the dataset)
#define NNODES 100000
#define NEDGES 1600000
#define NGRAPH 128
#define HDIM   128
#define FDIM   64
#define LN_EPS 1e-5f

#define SCANW   1024
#define NSCANBLK ((NNODES + SCANW) / SCANW + 1)
#define NPARTIAL (NSCANBLK * SCANW)

// ---------------- scratch (device globals; no allocations allowed) ----------
__device__ int   g_ibuf[NPARTIAL + NNODES];         // deg + fill cursors (one memset)
__device__ int   g_partial[NPARTIAL];               // per-block exclusive scan
__device__ int   g_blocksum[256];
__device__ int   g_blockpref[128];                  // written by k_fill block 0
__device__ int2  g_csr[NEDGES];                     // (src, bits(dinv[src]))
__device__ float g_bufa[(size_t)NNODES * HDIM];
__device__ float g_bufb[(size_t)NNODES * HDIM];
__device__ float g_pool[NGRAPH * HDIM + NGRAPH];    // gsum + gcnt (one memset)

// ---------------- degree count ----------------
__global__ void k_count_deg(const int* __restrict__ dst, int* __restrict__ deg, int e) {
    int i = blockIdx.x * blockDim.x + threadIdx.x;
    if (i < e) atomicAdd(&deg[dst[i]], 1);
}

// ---------------- per-block exclusive scan (level 1) ----------------
__global__ void k_scan_block(const int* __restrict__ deg, int* __restrict__ partial,
                             int* __restrict__ blocksum, int n) {
    __shared__ int sm[2][SCANW];
    int t = threadIdx.x;
    int g = blockIdx.x * SCANW + t;
    int v = (g < n) ? deg[g] : 0;
    sm[0][t] = v;
    __syncthreads();
    int cur = 0;
#pragma unroll
    for (int off = 1; off < SCANW; off <<= 1) {
        int x = sm[cur][t];
        if (t >= off) x += sm[cur][t - off];
        sm[cur ^ 1][t] = x;
        __syncthreads();
        cur ^= 1;
    }
    int inc = sm[cur][t];
    partial[g] = inc - v;
    if (t == SCANW - 1) blocksum[blockIdx.x] = inc;
}

// Level-2 prefix computed in-block (<=128 scan blocks). All threads call it.
__device__ __forceinline__ void block_prefix(const int* __restrict__ bsum, int B,
                                             int* __restrict__ sbp) {
    __shared__ int tmp[128];
    int t = threadIdx.x;
    int v = 0;
    if (t < 128) { v = (t < B) ? bsum[t] : 0; tmp[t] = v; }
    __syncthreads();
#pragma unroll
    for (int off = 1; off < 128; off <<= 1) {
        int x = 0;
        if (t < 128) { x = tmp[t]; if (t >= off) x += tmp[t - off]; }
        __syncthreads();
        if (t < 128) tmp[t] = x;
        __syncthreads();
    }
    if (t < 128) sbp[t] = tmp[t] - v;   // exclusive
    __syncthreads();
}

// ---------------- CSR fill (also publishes the level-2 prefix) --------------
__global__ void __launch_bounds__(256)
k_fill(const int* __restrict__ src, const int* __restrict__ dst,
       const int* __restrict__ deg, const int* __restrict__ partial,
       const int* __restrict__ bsum, int B, int* __restrict__ bpref_g,
       int* __restrict__ cnt2, int2* __restrict__ csr, int e) {
    __shared__ int sbp[128];
    block_prefix(bsum, B, sbp);
    if (blockIdx.x == 0 && threadIdx.x < 128) bpref_g[threadIdx.x] = sbp[threadIdx.x];
    int i = blockIdx.x * blockDim.x + threadIdx.x;
    if (i >= e) return;
    int s = src[i];
    int d = dst[i];
    float dvs = rsqrtf((float)(deg[s] + 1));
    int pos = partial[d] + sbp[d >> 10] + atomicAdd(&cnt2[d], 1);
    csr[pos] = make_int2(s, __float_as_int(dvs));
}

// ---------------- FUSED gather-aggregate + GEMM + bias + LN (+ReLU) ---------
// Phase 1: 8 warps aggregate 4 nodes each (warp-per-node gather over CSR),
//          writing the aggregated 32xK X-tile straight into SMEM.
// Phase 2: X @ W with bias + LayerNorm (+ReLU) epilogue (R4-proven FFMA core).
// out[v,:] = LN( [dinv_v*(sum dinv_s*feat_s + dinv_v*feat_v)] @ W + b )
template <int K, bool RELU>
__global__ void __launch_bounds__(256)
k_agg_gemm_ln(const float* __restrict__ feat, const int* __restrict__ deg,
              const int2* __restrict__ csr, const int* __restrict__ partial,
              const int* __restrict__ bpref,
              const float* __restrict__ W, const float* __restrict__ bias,
              const float* __restrict__ gamma, const float* __restrict__ beta,
              float* __restrict__ out, int n) {
    __shared__ __align__(16) float sW[32][128];
    __shared__ __align__(16) float sX[32][K + 4];   // row-major, +4 pad (16B-mult stride)

    const int tid  = threadIdx.x;
    const int warp = tid >> 5;
    const int lane = tid & 31;
    const int row0 = blockIdx.x * 32;   // n divisible by 32

    // ---------------- phase 1: aggregation into sX ----------------
#pragma unroll
    for (int i = 0; i < 4; i++) {
        const int w = row0 + warp * 4 + i;
        const int r0 = partial[w] + bpref[w >> 10];
        const int r1 = partial[w + 1] + bpref[(w + 1) >> 10];
        const float dv = rsqrtf((float)(deg[w] + 1));

        if (K == 64) {
            float2 acc = reinterpret_cast<const float2*>(feat)[(size_t)w * 32 + lane];
            acc.x *= dv; acc.y *= dv;
            int r = r0;
            for (; r + 4 <= r1; r += 4) {
                int2 e0 = csr[r], e1 = csr[r + 1], e2 = csr[r + 2], e3 = csr[r + 3];
                float2 v0 = reinterpret_cast<const float2*>(feat)[(size_t)e0.x * 32 + lane];
                float2 v1 = reinterpret_cast<const float2*>(feat)[(size_t)e1.x * 32 + lane];
                float2 v2 = reinterpret_cast<const float2*>(feat)[(size_t)e2.x * 32 + lane];
                float2 v3 = reinterpret_cast<const float2*>(feat)[(size_t)e3.x * 32 + lane];
                float w0 = __int_as_float(e0.y), w1 = __int_as_float(e1.y);
                float w2 = __int_as_float(e2.y), w3 = __int_as_float(e3.y);
                acc.x = fmaf(w0, v0.x, acc.x); acc.y = fmaf(w0, v0.y, acc.y);
                acc.x = fmaf(w1, v1.x, acc.x); acc.y = fmaf(w1, v1.y, acc.y);
                acc.x = fmaf(w2, v2.x, acc.x); acc.y = fmaf(w2, v2.y, acc.y);
                acc.x = fmaf(w3, v3.x, acc.x); acc.y = fmaf(w3, v3.y, acc.y);
            }
            for (; r < r1; r++) {
                int2 e0 = csr[r];
                float2 v0 = reinterpret_cast<const float2*>(feat)[(size_t)e0.x * 32 + lane];
                float w0 = __int_as_float(e0.y);
                acc.x = fmaf(w0, v0.x, acc.x); acc.y = fmaf(w0, v0.y, acc.y);
            }
            acc.x *= dv; acc.y *= dv;
            *reinterpret_cast<float2*>(&sX[warp * 4 + i][lane * 2]) = acc;
        } else {
            float4 acc = reinterpret_cast<const float4*>(feat)[(size_t)w * 32 + lane];
            acc.x *= dv; acc.y *= dv; acc.z *= dv; acc.w *= dv;
            int r = r0;
            for (; r + 4 <= r1; r += 4) {
                int2 e0 = csr[r], e1 = csr[r + 1], e2 = csr[r + 2], e3 = csr[r + 3];
                float4 v0 = reinterpret_cast<const float4*>(feat)[(size_t)e0.x * 32 + lane];
                float4 v1 = reinterpret_cast<const float4*>(feat)[(size_t)e1.x * 32 + lane];
                float4 v2 = reinterpret_cast<const float4*>(feat)[(size_t)e2.x * 32 + lane];
                float4 v3 = reinterpret_cast<const float4*>(feat)[(size_t)e3.x * 32 + lane];
                float w0 = __int_as_float(e0.y), w1 = __int_as_float(e1.y);
                float w2 = __int_as_float(e2.y), w3 = __int_as_float(e3.y);
                acc.x = fmaf(w0, v0.x, acc.x); acc.y = fmaf(w0, v0.y, acc.y);
                acc.z = fmaf(w0, v0.z, acc.z); acc.w = fmaf(w0, v0.w, acc.w);
                acc.x = fmaf(w1, v1.x, acc.x); acc.y = fmaf(w1, v1.y, acc.y);
                acc.z = fmaf(w1, v1.z, acc.z); acc.w = fmaf(w1, v1.w, acc.w);
                acc.x = fmaf(w2, v2.x, acc.x); acc.y = fmaf(w2, v2.y, acc.y);
                acc.z = fmaf(w2, v2.z, acc.z); acc.w = fmaf(w2, v2.w, acc.w);
                acc.x = fmaf(w3, v3.x, acc.x); acc.y = fmaf(w3, v3.y, acc.y);
                acc.z = fmaf(w3, v3.z, acc.z); acc.w = fmaf(w3, v3.w, acc.w);
            }
            for (; r < r1; r++) {
                int2 e0 = csr[r];
                float4 v0 = reinterpret_cast<const float4*>(feat)[(size_t)e0.x * 32 + lane];
                float w0 = __int_as_float(e0.y);
                acc.x = fmaf(w0, v0.x, acc.x); acc.y = fmaf(w0, v0.y, acc.y);
                acc.z = fmaf(w0, v0.z, acc.z); acc.w = fmaf(w0, v0.w, acc.w);
            }
            acc.x *= dv; acc.y *= dv; acc.z *= dv; acc.w *= dv;
            *reinterpret_cast<float4*>(&sX[warp * 4 + i][lane * 4]) = acc;
        }
    }
    __syncthreads();

    // ---------------- phase 2: GEMM + LN ----------------
    float acc[4][4];
#pragma unroll
    for (int r = 0; r < 4; r++)
#pragma unroll
        for (int c = 0; c < 4; c++) acc[r][c] = 0.0f;

#pragma unroll
    for (int kt = 0; kt < K; kt += 32) {
        // stage W chunk: 32x128 floats = 1024 float4, 256 threads -> 4 each
#pragma unroll
        for (int i = tid; i < 1024; i += 256) {
            int kk = i >> 5;
            int c4 = i & 31;
            reinterpret_cast<float4*>(sW[kk])[c4] =
                reinterpret_cast<const float4*>(W + (size_t)(kt + kk) * 128)[c4];
        }
        __syncthreads();

#pragma unroll
        for (int kk = 0; kk < 32; kk++) {
            float4 wv = reinterpret_cast<float4*>(sW[kk])[lane];
#pragma unroll
            for (int r = 0; r < 4; r++) {
                float xv = sX[warp * 4 + r][kt + kk];
                acc[r][0] = fmaf(xv, wv.x, acc[r][0]);
                acc[r][1] = fmaf(xv, wv.y, acc[r][1]);
                acc[r][2] = fmaf(xv, wv.z, acc[r][2]);
                acc[r][3] = fmaf(xv, wv.w, acc[r][3]);
            }
        }
        __syncthreads();
    }

    const float4 bv = reinterpret_cast<const float4*>(bias)[lane];
    const float4 gv = reinterpret_cast<const float4*>(gamma)[lane];
    const float4 be = reinterpret_cast<const float4*>(beta)[lane];

#pragma unroll
    for (int r = 0; r < 4; r++) {
        float hx = acc[r][0] + bv.x;
        float hy = acc[r][1] + bv.y;
        float hz = acc[r][2] + bv.z;
        float hw = acc[r][3] + bv.w;
        float s = hx + hy + hz + hw;
#pragma unroll
        for (int o = 16; o > 0; o >>= 1) s += __shfl_xor_sync(0xffffffffu, s, o);
        float mu = s * (1.0f / 128.0f);
        float dx = hx - mu, dy = hy - mu, dz = hz - mu, dw = hw - mu;
        float q = dx * dx + dy * dy + dz * dz + dw * dw;
#pragma unroll
        for (int o = 16; o > 0; o >>= 1) q += __shfl_xor_sync(0xffffffffu, q, o);
        float rstd = rsqrtf(q * (1.0f / 128.0f) + LN_EPS);

        float4 o4;
        o4.x = dx * rstd * gv.x + be.x;
        o4.y = dy * rstd * gv.y + be.y;
        o4.z = dz * rstd * gv.z + be.z;
        o4.w = dw * rstd * gv.w + be.w;
        if (RELU) {
            o4.x = fmaxf(o4.x, 0.0f);
            o4.y = fmaxf(o4.y, 0.0f);
            o4.z = fmaxf(o4.z, 0.0f);
            o4.w = fmaxf(o4.w, 0.0f);
        }
        int row = row0 + warp * 4 + r;
        reinterpret_cast<float4*>(out + (size_t)row * 128)[lane] = o4;
    }
}

// ---------------- pooling (batch is sorted; count fused) ----------------
__global__ void k_pool_sum(const float* __restrict__ h, const int* __restrict__ batch,
                           float* __restrict__ gsum, int* __restrict__ gcnt, int n, int rpb) {
    int c  = threadIdx.x;
    int r0 = blockIdx.x * rpb;
    int r1 = min(r0 + rpb, n);
    if (r0 >= r1) return;
    float acc = 0.0f;
    int cnt = 0;
    int cur = batch[r0];
    for (int r = r0; r < r1; r++) {
        int g = batch[r];
        if (g != cur) {
            atomicAdd(&gsum[cur * HDIM + c], acc);
            if (c == 0) atomicAdd(&gcnt[cur], cnt);
            acc = 0.0f; cnt = 0; cur = g;
        }
        acc += h[(size_t)r * HDIM + c];
        cnt++;
    }
    atomicAdd(&gsum[cur * HDIM + c], acc);
    if (c == 0) atomicAdd(&gcnt[cur], cnt);
}

__global__ void k_finalize(const float* __restrict__ gsum, const int* __restrict__ gcnt,
                           float* __restrict__ out) {
    int i = blockIdx.x * blockDim.x + threadIdx.x;
    if (i >= NGRAPH * HDIM) return;
    float cnt = fmaxf((float)gcnt[i >> 7], 1.0f);
    out[i] = gsum[i] / cnt;
}

// ---------------- launch ----------------
extern "C" void kernel_launch(void* const* d_in, const int* in_sizes, int n_in,
                              void* d_out, int out_size) {
    const float* x     = (const float*)d_in[0];
    const int*   eidx  = (const int*)d_in[1];
    const int*   batch = (const int*)d_in[2];
    const float* W1 = (const float*)d_in[3];
    const float* b1 = (const float*)d_in[4];
    const float* g1 = (const float*)d_in[5];
    const float* be1 = (const float*)d_in[6];
    const float* W2 = (const float*)d_in[7];
    const float* b2 = (const float*)d_in[8];
    const float* g2 = (const float*)d_in[9];
    const float* be2 = (const float*)d_in[10];

    const int n = in_sizes[0] / FDIM;   // 100000
    const int e = in_sizes[1] / 2;      // 1600000
    const int* src = eidx;
    const int* dst = eidx + e;

    int*   ibuf;  cudaGetSymbolAddress((void**)&ibuf,  g_ibuf);
    int*   part;  cudaGetSymbolAddress((void**)&part,  g_partial);
    int*   bsum;  cudaGetSymbolAddress((void**)&bsum,  g_blocksum);
    int*   bpref; cudaGetSymbolAddress((void**)&bpref, g_blockpref);
    int2*  csr;   cudaGetSymbolAddress((void**)&csr,   g_csr);
    float* bufa;  cudaGetSymbolAddress((void**)&bufa,  g_bufa);
    float* bufb;  cudaGetSymbolAddress((void**)&bufb,  g_bufb);
    float* pool;  cudaGetSymbolAddress((void**)&pool,  g_pool);

    int* deg  = ibuf;
    int* cnt2 = ibuf + NPARTIAL;
    float* gsum = pool;
    int*   gcnt = (int*)(pool + NGRAPH * HDIM);

    const int T = 256;
    auto cdiv = [](int a, int b) { return (a + b - 1) / b; };
    const int B = cdiv(n + 1, SCANW);   // scan blocks (covers index n)

    cudaMemsetAsync(ibuf, 0, sizeof(int) * (NPARTIAL + NNODES));
    cudaMemsetAsync(pool, 0, sizeof(float) * (NGRAPH * HDIM) + sizeof(int) * NGRAPH);

    // CSR build
    k_count_deg<<<cdiv(e, T), T>>>(dst, deg, e);                                   // 1
    k_scan_block<<<B, SCANW>>>(deg, part, bsum, n);                                // 2
    k_fill<<<cdiv(e, T), T>>>(src, dst, deg, part, bsum, B, bpref, cnt2, csr, e);  // 3

    // conv1 fused: agg64(x) -> GEMM(W1) -> LN -> ReLU -> bufb
    k_agg_gemm_ln<FDIM, true><<<n / 32, T>>>(x, deg, csr, part, bpref,
                                             W1, b1, g1, be1, bufb, n);            // 4 <- profiled
    // conv2 fused: agg128(bufb) -> GEMM(W2) -> LN -> bufa
    k_agg_gemm_ln<HDIM, false><<<n / 32, T>>>(bufb, deg, csr, part, bpref,
                                              W2, b2, g2, be2, bufa, n);           // 5

    // mean pool per graph (batch is sorted)
    const int rpb = 128;
    k_pool_sum<<<cdiv(n, rpb), HDIM>>>(bufa, batch, gsum, gcnt, n, rpb);           // 6
    k_finalize<<<cdiv(NGRAPH * HDIM, HDIM), HDIM>>>(gsum, gcnt, (float*)d_out);    // 7
}